// round 3
// baseline (speedup 1.0000x reference)
#include <cuda_runtime.h>
#include <cuda_bf16.h>
#include <math.h>

#define H_   16
#define KV_  8
#define D_   128
#define HID_ 2048
#define Q_   1024
#define S_   8192

// ---------------- scratch (device globals: no allocation allowed) ----------------
__device__ float g_q   [HID_ * Q_];        // q projection  [2048][1024]
__device__ float g_k   [KV_ * D_ * Q_];    // k projection  [1024][1024]
__device__ float g_v   [KV_ * D_ * Q_];    // v projection  [1024][1024]
__device__ float g_qt  [H_ * Q_ * D_];     // q after RoPE, [h][i][d], pre-scaled by 1/sqrt(D)
__device__ float g_knew[KV_ * Q_ * D_];    // new K after RoPE, [kv][i][d]
__device__ float g_vnew[KV_ * Q_ * D_];    // new V transposed, [kv][i][d]
__device__ float g_attnT[Q_ * HID_];       // attention out, transposed [q][c]

// ---------------- SGEMM: C[M,N] = A[M,K] * B + bias, 64x64x16 tiles ----------------
// BT=false: B is [K][N] row-major.  BT=true: B is [N][K] row-major (B transposed).
template<bool BT>
__global__ __launch_bounds__(256)
void sgemm_kernel(const float* __restrict__ A, const float* __restrict__ B,
                  const float* __restrict__ bias, float* __restrict__ C,
                  int M, int N, int K)
{
    __shared__ float As[16][68];
    __shared__ float Bs[16][68];
    const int tid = threadIdx.x;
    const int tx = tid & 15, ty = tid >> 4;
    const int m0 = blockIdx.y * 64, n0 = blockIdx.x * 64;

    float acc[4][4];
#pragma unroll
    for (int a = 0; a < 4; a++)
#pragma unroll
        for (int b = 0; b < 4; b++) acc[a][b] = 0.f;

    const int arow = tid >> 2;          // 0..63
    const int akc  = (tid & 3) * 4;     // 0,4,8,12

    for (int k0 = 0; k0 < K; k0 += 16) {
        // A tile: 64 rows x 16 k, float4 loads, transposed scalar stores
        float4 a4 = *(const float4*)&A[(size_t)(m0 + arow) * K + k0 + akc];
        As[akc + 0][arow] = a4.x; As[akc + 1][arow] = a4.y;
        As[akc + 2][arow] = a4.z; As[akc + 3][arow] = a4.w;
        if (!BT) {
            int brow = tid >> 4;            // 0..15
            int bnc  = (tid & 15) * 4;      // 0..60
            float4 b4 = *(const float4*)&B[(size_t)(k0 + brow) * N + n0 + bnc];
            *(float4*)&Bs[brow][bnc] = b4;  // row stride 68 floats = 272B, 16B aligned
        } else {
            float4 b4 = *(const float4*)&B[(size_t)(n0 + arow) * K + k0 + akc];
            Bs[akc + 0][arow] = b4.x; Bs[akc + 1][arow] = b4.y;
            Bs[akc + 2][arow] = b4.z; Bs[akc + 3][arow] = b4.w;
        }
        __syncthreads();
#pragma unroll
        for (int kk = 0; kk < 16; kk++) {
            float ar[4], br[4];
#pragma unroll
            for (int x = 0; x < 4; x++) ar[x] = As[kk][ty + 16 * x];
#pragma unroll
            for (int x = 0; x < 4; x++) br[x] = Bs[kk][tx + 16 * x];
#pragma unroll
            for (int a = 0; a < 4; a++)
#pragma unroll
                for (int b = 0; b < 4; b++)
                    acc[a][b] = fmaf(ar[a], br[b], acc[a][b]);
        }
        __syncthreads();
    }
#pragma unroll
    for (int a = 0; a < 4; a++) {
        int m = m0 + ty + 16 * a;
        float bv = bias ? bias[m] : 0.f;
#pragma unroll
        for (int b = 0; b < 4; b++)
            C[(size_t)m * N + n0 + tx + 16 * b] = acc[a][b] + bv;
    }
}

// -------- RoPE + transpose: src [nh*128][Q] -> dst [nh][Q][128], optional rope --------
// cos/sin tables in (Q, D) layout (the non-transposed ones): fully coalesced.
__global__ __launch_bounds__(256)
void rope_transpose_kernel(const float* __restrict__ src, const float* __restrict__ cosQD,
                           const float* __restrict__ sinQD, float* __restrict__ dst,
                           float scale, int do_rope)
{
    __shared__ float tile[128][33];
    const int tx = threadIdx.x, ty = threadIdx.y;   // 32 x 8
    const int i0 = blockIdx.x * 32;
    const int h  = blockIdx.y;
#pragma unroll
    for (int r = 0; r < 16; r++) {
        int row = r * 8 + ty;   // 0..127 (d)
        tile[row][tx] = src[(size_t)(h * 128 + row) * Q_ + i0 + tx];
    }
    __syncthreads();
    const int t = ty * 32 + tx;
#pragma unroll
    for (int r = 0; r < 16; r++) {
        int idx = r * 256 + t;
        int d = idx & 127, i = idx >> 7;
        float v = tile[d][i];
        float out;
        if (do_rope) {
            float o = (d < 64) ? -tile[d + 64][i] : tile[d - 64][i];
            float c = cosQD[(size_t)(i0 + i) * 128 + d];
            float s = sinQD[(size_t)(i0 + i) * 128 + d];
            out = (v * c + o * s) * scale;
        } else {
            out = v;
        }
        dst[(size_t)(h * Q_ + i0 + i) * 128 + d] = out;
    }
}

// ---------------- flash attention: BQ=64 queries x BS=32 keys per step ----------------
// grid (Q/64, H). q pre-scaled by 1/sqrt(D). Causal mask analytic (== reference mask).
// K/V gathered from cache for s<cpos or s>=cpos+Q, else from RoPE'd new K/V.
// Output written transposed [q][h*128+d] with coalesced float4 stores.
__global__ __launch_bounds__(256)
void attn_kernel(const float* __restrict__ qt, const float* __restrict__ knew,
                 const float* __restrict__ vnew, const float* __restrict__ kcache,
                 const float* __restrict__ vcache, const int* __restrict__ cpos_p,
                 float* __restrict__ outT)
{
    extern __shared__ float sm[];
    float* sQ   = sm;                   // 64*128
    float* sK   = sQ + 64 * 128;        // 32*129 (padded)
    float* sV   = sK + 32 * 129;        // 32*128
    float* sS   = sV + 32 * 128;        // 64*33  (probs)
    float* m_s  = sS + 64 * 33;         // 64
    float* l_s  = m_s + 64;             // 64
    float* sc_s = l_s + 64;             // 64

    const int tid = threadIdx.x;
    const int q0  = blockIdx.x * 64;
    const int h   = blockIdx.y;
    const int kv  = h >> 1;             // GQA: G = H/KV = 2
    const int cpos = cpos_p[0];

    if (tid < 64) { m_s[tid] = -1e30f; l_s[tid] = 0.f; }

    // load Q tile (64 x 128), coalesced float4
#pragma unroll
    for (int r = 0; r < 8; r++) {
        int idx = r * 256 + tid;
        int i = idx >> 5, c4 = (idx & 31) << 2;
        *(float4*)&sQ[i * 128 + c4] =
            *(const float4*)&qt[(size_t)(h * Q_ + q0 + i) * 128 + c4];
    }

    const int lane = tid & 31, w = tid >> 5;    // PV mapping: d = lane*4, rows i = w+8*wi
    const int tx = tid & 15, ty = tid >> 4;     // score mapping: j = tx+16b, i = ty+16a

    float acc[8][4];
#pragma unroll
    for (int a = 0; a < 8; a++)
#pragma unroll
        for (int c = 0; c < 4; c++) acc[a][c] = 0.f;

    int nblk = (cpos + q0 + 63) / 32 + 1;       // last visible key = cpos + q0 + 63
    if (nblk > S_ / 32) nblk = S_ / 32;

    for (int sb = 0; sb < nblk; sb++) {
        const int s0 = sb * 32;
        __syncthreads();    // protect sK/sV/sS reuse + m_s/l_s ordering

        // load K (scalar stores into padded rows) and V (float4) tiles
#pragma unroll
        for (int r = 0; r < 4; r++) {
            int idx = r * 256 + tid;
            int j = idx >> 5, c4 = (idx & 31) << 2;
            int s = s0 + j;
            bool is_new = (s >= cpos) && (s < cpos + Q_);
            const float* srck = is_new ? &knew[(size_t)(kv * Q_ + (s - cpos)) * 128]
                                       : &kcache[(size_t)(kv * S_ + s) * 128];
            float4 kk4 = *(const float4*)&srck[c4];
            sK[j * 129 + c4 + 0] = kk4.x; sK[j * 129 + c4 + 1] = kk4.y;
            sK[j * 129 + c4 + 2] = kk4.z; sK[j * 129 + c4 + 3] = kk4.w;
            const float* srcv = is_new ? &vnew[(size_t)(kv * Q_ + (s - cpos)) * 128]
                                       : &vcache[(size_t)(kv * S_ + s) * 128];
            *(float4*)&sV[j * 128 + c4] = *(const float4*)&srcv[c4];
        }
        __syncthreads();

        // ---- scores: 64x32, each thread 4 rows x 2 cols ----
        float scr[4][2];
#pragma unroll
        for (int a = 0; a < 4; a++) { scr[a][0] = 0.f; scr[a][1] = 0.f; }
#pragma unroll 4
        for (int d = 0; d < 128; d++) {
            float k0v = sK[tx * 129 + d];
            float k1v = sK[(tx + 16) * 129 + d];
#pragma unroll
            for (int a = 0; a < 4; a++) {
                float qv = sQ[(ty + 16 * a) * 128 + d];
                scr[a][0] = fmaf(qv, k0v, scr[a][0]);
                scr[a][1] = fmaf(qv, k1v, scr[a][1]);
            }
        }

        // ---- mask + online softmax (rows owned by 16-lane half-warps) ----
#pragma unroll
        for (int a = 0; a < 4; a++) {
            int i = ty + 16 * a;
            int lim = cpos + q0 + i;                 // key s visible iff s <= lim
            if (s0 + tx      > lim) scr[a][0] = -1e30f;
            if (s0 + tx + 16 > lim) scr[a][1] = -1e30f;
            float mx = fmaxf(scr[a][0], scr[a][1]);
#pragma unroll
            for (int o = 8; o >= 1; o >>= 1)
                mx = fmaxf(mx, __shfl_xor_sync(0xffffffffu, mx, o));
            float m_old = m_s[i];
            float m_new = fmaxf(m_old, mx);
            float p0 = __expf(scr[a][0] - m_new);
            float p1 = __expf(scr[a][1] - m_new);
            sS[i * 33 + tx]      = p0;
            sS[i * 33 + tx + 16] = p1;
            float ls = p0 + p1;
#pragma unroll
            for (int o = 8; o >= 1; o >>= 1)
                ls += __shfl_xor_sync(0xffffffffu, ls, o);
            if (tx == 0) {
                float scl = __expf(m_old - m_new);
                sc_s[i] = scl;
                l_s[i]  = l_s[i] * scl + ls;
                m_s[i]  = m_new;
            }
        }
        __syncthreads();

        // ---- PV accumulate: thread owns d-chunk lane*4, rows w+8*wi ----
#pragma unroll
        for (int wi = 0; wi < 8; wi++) {
            float s = sc_s[w + 8 * wi];
            acc[wi][0] *= s; acc[wi][1] *= s; acc[wi][2] *= s; acc[wi][3] *= s;
        }
#pragma unroll 4
        for (int j = 0; j < 32; j++) {
            float4 v4 = *(const float4*)&sV[j * 128 + lane * 4];
#pragma unroll
            for (int wi = 0; wi < 8; wi++) {
                float p = sS[(w + 8 * wi) * 33 + j];
                acc[wi][0] = fmaf(p, v4.x, acc[wi][0]);
                acc[wi][1] = fmaf(p, v4.y, acc[wi][1]);
                acc[wi][2] = fmaf(p, v4.z, acc[wi][2]);
                acc[wi][3] = fmaf(p, v4.w, acc[wi][3]);
            }
        }
    }
    __syncthreads();

    // epilogue: normalize + coalesced float4 stores into transposed layout [q][c]
#pragma unroll
    for (int wi = 0; wi < 8; wi++) {
        int i = w + 8 * wi;
        float inv = 1.f / l_s[i];
        float4 o4 = make_float4(acc[wi][0] * inv, acc[wi][1] * inv,
                                acc[wi][2] * inv, acc[wi][3] * inv);
        *(float4*)&outT[(size_t)(q0 + i) * HID_ + h * 128 + lane * 4] = o4;
    }
}

// ---------------- launch ----------------
extern "C" void kernel_launch(void* const* d_in, const int* in_sizes, int n_in,
                              void* d_out, int out_size)
{
    const float* hidden = (const float*)d_in[0];   // (1,2048,1,1024)
    const float* cosQD  = (const float*)d_in[1];   // (1,1,Q,D)
    const float* sinQD  = (const float*)d_in[2];   // (1,1,Q,D)
    // d_in[3]=cos_t, d_in[4]=sin_t, d_in[5]=attention_mask: unused (mask is analytic causal)
    const float* kcache = (const float*)d_in[6];   // (1,KV,S,D)
    const float* vcache = (const float*)d_in[7];
    const float* Wq = (const float*)d_in[8];
    const float* bq = (const float*)d_in[9];
    const float* Wk = (const float*)d_in[10];
    const float* bk = (const float*)d_in[11];
    const float* Wv = (const float*)d_in[12];
    const float* bv = (const float*)d_in[13];
    const float* Wo = (const float*)d_in[14];
    const int*   cpos = (const int*)d_in[15];      // 4096 (little-endian: int32/int64 both ok)
    float* out = (float*)d_out;

    float *pq, *pk, *pv, *pqt, *pkn, *pvn, *pat;
    cudaGetSymbolAddress((void**)&pq,  g_q);
    cudaGetSymbolAddress((void**)&pk,  g_k);
    cudaGetSymbolAddress((void**)&pv,  g_v);
    cudaGetSymbolAddress((void**)&pqt, g_qt);
    cudaGetSymbolAddress((void**)&pkn, g_knew);
    cudaGetSymbolAddress((void**)&pvn, g_vnew);
    cudaGetSymbolAddress((void**)&pat, g_attnT);

    // 1) projections (C = W * hidden + b), hidden is [HID][Q]
    sgemm_kernel<false><<<dim3(Q_ / 64, HID_ / 64), 256>>>(Wq, hidden, bq, pq, HID_, Q_, HID_);
    sgemm_kernel<false><<<dim3(Q_ / 64, (KV_ * D_) / 64), 256>>>(Wk, hidden, bk, pk, KV_ * D_, Q_, HID_);
    sgemm_kernel<false><<<dim3(Q_ / 64, (KV_ * D_) / 64), 256>>>(Wv, hidden, bv, pv, KV_ * D_, Q_, HID_);

    // 2) RoPE + transpose to [head][q][d]; q gets 1/sqrt(D) folded in
    rope_transpose_kernel<<<dim3(Q_ / 32, H_),  dim3(32, 8)>>>(pq, cosQD, sinQD, pqt, 0.08838834764831845f, 1);
    rope_transpose_kernel<<<dim3(Q_ / 32, KV_), dim3(32, 8)>>>(pk, cosQD, sinQD, pkn, 1.0f, 1);
    rope_transpose_kernel<<<dim3(Q_ / 32, KV_), dim3(32, 8)>>>(pv, nullptr, nullptr, pvn, 1.0f, 0);

    // 3) flash attention over cache + new KV
    const size_t ATTN_SMEM = (size_t)(64 * 128 + 32 * 129 + 32 * 128 + 64 * 33 + 3 * 64) * sizeof(float);
    cudaFuncSetAttribute(attn_kernel, cudaFuncAttributeMaxDynamicSharedMemorySize, (int)ATTN_SMEM);
    attn_kernel<<<dim3(Q_ / 64, H_), 256, ATTN_SMEM>>>(pqt, pkn, pvn, kcache, vcache, cpos, pat);

    // 4) output projection: out = Wo * attn, attn stored transposed [q][c]
    sgemm_kernel<true><<<dim3(Q_ / 64, HID_ / 64), 256>>>(Wo, pat, nullptr, out, HID_, Q_, HID_);
}

// round 4
// speedup vs baseline: 1.0012x; 1.0012x over previous
#include <cuda_runtime.h>
#include <cuda_bf16.h>
#include <math.h>

#define H_   16
#define KV_  8
#define D_   128
#define HID_ 2048
#define Q_   1024
#define S_   8192

// ---------------- scratch (device globals: no allocation allowed) ----------------
__device__ float g_q   [HID_ * Q_];        // q projection  [2048][1024]
__device__ float g_k   [KV_ * D_ * Q_];    // k projection  [1024][1024]
__device__ float g_v   [KV_ * D_ * Q_];    // v projection  [1024][1024]
__device__ float g_qt  [H_ * Q_ * D_];     // q after RoPE, [h][i][d], pre-scaled by 1/sqrt(D)
__device__ float g_knew[KV_ * Q_ * D_];    // new K after RoPE, [kv][i][d]
__device__ float g_vnew[KV_ * Q_ * D_];    // new V transposed, [kv][i][d]
__device__ float g_attnT[Q_ * HID_];       // attention out, transposed [q][c]

// ---------------- SGEMM: C[M,N] = A[M,K] * B + bias, 64x64x16 tiles ----------------
// BT=false: B is [K][N] row-major.  BT=true: B is [N][K] row-major (B transposed).
template<bool BT>
__global__ __launch_bounds__(256)
void sgemm_kernel(const float* __restrict__ A, const float* __restrict__ B,
                  const float* __restrict__ bias, float* __restrict__ C,
                  int M, int N, int K)
{
    __shared__ float As[16][68];
    __shared__ float Bs[16][68];
    const int tid = threadIdx.x;
    const int tx = tid & 15, ty = tid >> 4;
    const int m0 = blockIdx.y * 64, n0 = blockIdx.x * 64;

    float acc[4][4];
#pragma unroll
    for (int a = 0; a < 4; a++)
#pragma unroll
        for (int b = 0; b < 4; b++) acc[a][b] = 0.f;

    const int arow = tid >> 2;          // 0..63
    const int akc  = (tid & 3) * 4;     // 0,4,8,12

    for (int k0 = 0; k0 < K; k0 += 16) {
        // A tile: 64 rows x 16 k, float4 loads, transposed scalar stores
        float4 a4 = *(const float4*)&A[(size_t)(m0 + arow) * K + k0 + akc];
        As[akc + 0][arow] = a4.x; As[akc + 1][arow] = a4.y;
        As[akc + 2][arow] = a4.z; As[akc + 3][arow] = a4.w;
        if (!BT) {
            int brow = tid >> 4;            // 0..15
            int bnc  = (tid & 15) * 4;      // 0..60
            float4 b4 = *(const float4*)&B[(size_t)(k0 + brow) * N + n0 + bnc];
            *(float4*)&Bs[brow][bnc] = b4;  // row stride 68 floats = 272B, 16B aligned
        } else {
            float4 b4 = *(const float4*)&B[(size_t)(n0 + arow) * K + k0 + akc];
            Bs[akc + 0][arow] = b4.x; Bs[akc + 1][arow] = b4.y;
            Bs[akc + 2][arow] = b4.z; Bs[akc + 3][arow] = b4.w;
        }
        __syncthreads();
#pragma unroll
        for (int kk = 0; kk < 16; kk++) {
            float ar[4], br[4];
#pragma unroll
            for (int x = 0; x < 4; x++) ar[x] = As[kk][ty + 16 * x];
#pragma unroll
            for (int x = 0; x < 4; x++) br[x] = Bs[kk][tx + 16 * x];
#pragma unroll
            for (int a = 0; a < 4; a++)
#pragma unroll
                for (int b = 0; b < 4; b++)
                    acc[a][b] = fmaf(ar[a], br[b], acc[a][b]);
        }
        __syncthreads();
    }
#pragma unroll
    for (int a = 0; a < 4; a++) {
        int m = m0 + ty + 16 * a;
        float bv = bias ? bias[m] : 0.f;
#pragma unroll
        for (int b = 0; b < 4; b++)
            C[(size_t)m * N + n0 + tx + 16 * b] = acc[a][b] + bv;
    }
}

// -------- RoPE + transpose: src [nh*128][Q] -> dst [nh][Q][128], optional rope --------
// cos/sin tables in (Q, D) layout (the non-transposed ones): fully coalesced.
__global__ __launch_bounds__(256)
void rope_transpose_kernel(const float* __restrict__ src, const float* __restrict__ cosQD,
                           const float* __restrict__ sinQD, float* __restrict__ dst,
                           float scale, int do_rope)
{
    __shared__ float tile[128][33];
    const int tx = threadIdx.x, ty = threadIdx.y;   // 32 x 8
    const int i0 = blockIdx.x * 32;
    const int h  = blockIdx.y;
#pragma unroll
    for (int r = 0; r < 16; r++) {
        int row = r * 8 + ty;   // 0..127 (d)
        tile[row][tx] = src[(size_t)(h * 128 + row) * Q_ + i0 + tx];
    }
    __syncthreads();
    const int t = ty * 32 + tx;
#pragma unroll
    for (int r = 0; r < 16; r++) {
        int idx = r * 256 + t;
        int d = idx & 127, i = idx >> 7;
        float v = tile[d][i];
        float out;
        if (do_rope) {
            float o = (d < 64) ? -tile[d + 64][i] : tile[d - 64][i];
            float c = cosQD[(size_t)(i0 + i) * 128 + d];
            float s = sinQD[(size_t)(i0 + i) * 128 + d];
            out = (v * c + o * s) * scale;
        } else {
            out = v;
        }
        dst[(size_t)(h * Q_ + i0 + i) * 128 + d] = out;
    }
}

// ---------------- flash attention: BQ=64 queries x BS=32 keys per step ----------------
// grid (Q/64, H). q pre-scaled by 1/sqrt(D). Causal mask analytic (== reference mask).
// K/V gathered from cache for s<cpos or s>=cpos+Q, else from RoPE'd new K/V.
// Output written transposed [q][h*128+d] with coalesced float4 stores.
__global__ __launch_bounds__(256)
void attn_kernel(const float* __restrict__ qt, const float* __restrict__ knew,
                 const float* __restrict__ vnew, const float* __restrict__ kcache,
                 const float* __restrict__ vcache, const int* __restrict__ cpos_p,
                 float* __restrict__ outT)
{
    extern __shared__ float sm[];
    float* sQ   = sm;                   // 64*128
    float* sK   = sQ + 64 * 128;        // 32*129 (padded)
    float* sV   = sK + 32 * 129;        // 32*128
    float* sS   = sV + 32 * 128;        // 64*33  (probs)
    float* m_s  = sS + 64 * 33;         // 64
    float* l_s  = m_s + 64;             // 64
    float* sc_s = l_s + 64;             // 64

    const int tid = threadIdx.x;
    const int q0  = blockIdx.x * 64;
    const int h   = blockIdx.y;
    const int kv  = h >> 1;             // GQA: G = H/KV = 2
    const int cpos = cpos_p[0];

    if (tid < 64) { m_s[tid] = -1e30f; l_s[tid] = 0.f; }

    // load Q tile (64 x 128), coalesced float4
#pragma unroll
    for (int r = 0; r < 8; r++) {
        int idx = r * 256 + tid;
        int i = idx >> 5, c4 = (idx & 31) << 2;
        *(float4*)&sQ[i * 128 + c4] =
            *(const float4*)&qt[(size_t)(h * Q_ + q0 + i) * 128 + c4];
    }

    const int lane = tid & 31, w = tid >> 5;    // PV mapping: d = lane*4, rows i = w+8*wi
    const int tx = tid & 15, ty = tid >> 4;     // score mapping: j = tx+16b, i = ty+16a

    float acc[8][4];
#pragma unroll
    for (int a = 0; a < 8; a++)
#pragma unroll
        for (int c = 0; c < 4; c++) acc[a][c] = 0.f;

    int nblk = (cpos + q0 + 63) / 32 + 1;       // last visible key = cpos + q0 + 63
    if (nblk > S_ / 32) nblk = S_ / 32;

    for (int sb = 0; sb < nblk; sb++) {
        const int s0 = sb * 32;
        __syncthreads();    // protect sK/sV/sS reuse + m_s/l_s ordering

        // load K (scalar stores into padded rows) and V (float4) tiles
#pragma unroll
        for (int r = 0; r < 4; r++) {
            int idx = r * 256 + tid;
            int j = idx >> 5, c4 = (idx & 31) << 2;
            int s = s0 + j;
            bool is_new = (s >= cpos) && (s < cpos + Q_);
            const float* srck = is_new ? &knew[(size_t)(kv * Q_ + (s - cpos)) * 128]
                                       : &kcache[(size_t)(kv * S_ + s) * 128];
            float4 kk4 = *(const float4*)&srck[c4];
            sK[j * 129 + c4 + 0] = kk4.x; sK[j * 129 + c4 + 1] = kk4.y;
            sK[j * 129 + c4 + 2] = kk4.z; sK[j * 129 + c4 + 3] = kk4.w;
            const float* srcv = is_new ? &vnew[(size_t)(kv * Q_ + (s - cpos)) * 128]
                                       : &vcache[(size_t)(kv * S_ + s) * 128];
            *(float4*)&sV[j * 128 + c4] = *(const float4*)&srcv[c4];
        }
        __syncthreads();

        // ---- scores: 64x32, each thread 4 rows x 2 cols ----
        float scr[4][2];
#pragma unroll
        for (int a = 0; a < 4; a++) { scr[a][0] = 0.f; scr[a][1] = 0.f; }
#pragma unroll 4
        for (int d = 0; d < 128; d++) {
            float k0v = sK[tx * 129 + d];
            float k1v = sK[(tx + 16) * 129 + d];
#pragma unroll
            for (int a = 0; a < 4; a++) {
                float qv = sQ[(ty + 16 * a) * 128 + d];
                scr[a][0] = fmaf(qv, k0v, scr[a][0]);
                scr[a][1] = fmaf(qv, k1v, scr[a][1]);
            }
        }

        // ---- mask + online softmax (rows owned by 16-lane half-warps) ----
#pragma unroll
        for (int a = 0; a < 4; a++) {
            int i = ty + 16 * a;
            int lim = cpos + q0 + i;                 // key s visible iff s <= lim
            if (s0 + tx      > lim) scr[a][0] = -1e30f;
            if (s0 + tx + 16 > lim) scr[a][1] = -1e30f;
            float mx = fmaxf(scr[a][0], scr[a][1]);
#pragma unroll
            for (int o = 8; o >= 1; o >>= 1)
                mx = fmaxf(mx, __shfl_xor_sync(0xffffffffu, mx, o));
            float m_old = m_s[i];
            float m_new = fmaxf(m_old, mx);
            float p0 = __expf(scr[a][0] - m_new);
            float p1 = __expf(scr[a][1] - m_new);
            sS[i * 33 + tx]      = p0;
            sS[i * 33 + tx + 16] = p1;
            float ls = p0 + p1;
#pragma unroll
            for (int o = 8; o >= 1; o >>= 1)
                ls += __shfl_xor_sync(0xffffffffu, ls, o);
            if (tx == 0) {
                float scl = __expf(m_old - m_new);
                sc_s[i] = scl;
                l_s[i]  = l_s[i] * scl + ls;
                m_s[i]  = m_new;
            }
        }
        __syncthreads();

        // ---- PV accumulate: thread owns d-chunk lane*4, rows w+8*wi ----
#pragma unroll
        for (int wi = 0; wi < 8; wi++) {
            float s = sc_s[w + 8 * wi];
            acc[wi][0] *= s; acc[wi][1] *= s; acc[wi][2] *= s; acc[wi][3] *= s;
        }
#pragma unroll 4
        for (int j = 0; j < 32; j++) {
            float4 v4 = *(const float4*)&sV[j * 128 + lane * 4];
#pragma unroll
            for (int wi = 0; wi < 8; wi++) {
                float p = sS[(w + 8 * wi) * 33 + j];
                acc[wi][0] = fmaf(p, v4.x, acc[wi][0]);
                acc[wi][1] = fmaf(p, v4.y, acc[wi][1]);
                acc[wi][2] = fmaf(p, v4.z, acc[wi][2]);
                acc[wi][3] = fmaf(p, v4.w, acc[wi][3]);
            }
        }
    }
    __syncthreads();

    // epilogue: normalize + coalesced float4 stores into transposed layout [q][c]
#pragma unroll
    for (int wi = 0; wi < 8; wi++) {
        int i = w + 8 * wi;
        float inv = 1.f / l_s[i];
        float4 o4 = make_float4(acc[wi][0] * inv, acc[wi][1] * inv,
                                acc[wi][2] * inv, acc[wi][3] * inv);
        *(float4*)&outT[(size_t)(q0 + i) * HID_ + h * 128 + lane * 4] = o4;
    }
}

// ---------------- launch ----------------
extern "C" void kernel_launch(void* const* d_in, const int* in_sizes, int n_in,
                              void* d_out, int out_size)
{
    const float* hidden = (const float*)d_in[0];   // (1,2048,1,1024)
    const float* cosQD  = (const float*)d_in[1];   // (1,1,Q,D)
    const float* sinQD  = (const float*)d_in[2];   // (1,1,Q,D)
    // d_in[3]=cos_t, d_in[4]=sin_t, d_in[5]=attention_mask: unused (mask is analytic causal)
    const float* kcache = (const float*)d_in[6];   // (1,KV,S,D)
    const float* vcache = (const float*)d_in[7];
    const float* Wq = (const float*)d_in[8];
    const float* bq = (const float*)d_in[9];
    const float* Wk = (const float*)d_in[10];
    const float* bk = (const float*)d_in[11];
    const float* Wv = (const float*)d_in[12];
    const float* bv = (const float*)d_in[13];
    const float* Wo = (const float*)d_in[14];
    const int*   cpos = (const int*)d_in[15];      // 4096 (little-endian: int32/int64 both ok)
    float* out = (float*)d_out;

    float *pq, *pk, *pv, *pqt, *pkn, *pvn, *pat;
    cudaGetSymbolAddress((void**)&pq,  g_q);
    cudaGetSymbolAddress((void**)&pk,  g_k);
    cudaGetSymbolAddress((void**)&pv,  g_v);
    cudaGetSymbolAddress((void**)&pqt, g_qt);
    cudaGetSymbolAddress((void**)&pkn, g_knew);
    cudaGetSymbolAddress((void**)&pvn, g_vnew);
    cudaGetSymbolAddress((void**)&pat, g_attnT);

    // 1) projections (C = W * hidden + b), hidden is [HID][Q]
    sgemm_kernel<false><<<dim3(Q_ / 64, HID_ / 64), 256>>>(Wq, hidden, bq, pq, HID_, Q_, HID_);
    sgemm_kernel<false><<<dim3(Q_ / 64, (KV_ * D_) / 64), 256>>>(Wk, hidden, bk, pk, KV_ * D_, Q_, HID_);
    sgemm_kernel<false><<<dim3(Q_ / 64, (KV_ * D_) / 64), 256>>>(Wv, hidden, bv, pv, KV_ * D_, Q_, HID_);

    // 2) RoPE + transpose to [head][q][d]; q gets 1/sqrt(D) folded in
    rope_transpose_kernel<<<dim3(Q_ / 32, H_),  dim3(32, 8)>>>(pq, cosQD, sinQD, pqt, 0.08838834764831845f, 1);
    rope_transpose_kernel<<<dim3(Q_ / 32, KV_), dim3(32, 8)>>>(pk, cosQD, sinQD, pkn, 1.0f, 1);
    rope_transpose_kernel<<<dim3(Q_ / 32, KV_), dim3(32, 8)>>>(pv, nullptr, nullptr, pvn, 1.0f, 0);

    // 3) flash attention over cache + new KV
    const size_t ATTN_SMEM = (size_t)(64 * 128 + 32 * 129 + 32 * 128 + 64 * 33 + 3 * 64) * sizeof(float);
    cudaFuncSetAttribute(attn_kernel, cudaFuncAttributeMaxDynamicSharedMemorySize, (int)ATTN_SMEM);
    attn_kernel<<<dim3(Q_ / 64, H_), 256, ATTN_SMEM>>>(pqt, pkn, pvn, kcache, vcache, cpos, pat);

    // 4) output projection: out = Wo * attn, attn stored transposed [q][c]
    sgemm_kernel<true><<<dim3(Q_ / 64, HID_ / 64), 256>>>(Wo, pat, nullptr, out, HID_, Q_, HID_);
}